// round 8
// baseline (speedup 1.0000x reference)
#include <cuda_runtime.h>
#include <cuda_fp16.h>
#include <cstdint>

static constexpr int BATCH = 65536;
static constexpr int KD    = 512;
static constexpr int ND    = 512;

static constexpr int BM = 64;
static constexpr int BN = 256;
static constexpr int BK = 32;            // 32 fp16 = 64B rows
static constexpr int NKITER = KD / BK;   // 16
static constexpr int STAGES = 3;

static constexpr int A_ST   = BM * BK * 2;              // 4096
static constexpr int B_ST   = BN * BK * 2;              // 16384
static constexpr int STAGE  = A_ST + B_ST;              // 20480
static constexpr int SMEM_TOTAL = STAGES * STAGE;       // 61440 (x3 CTAs = 180KB/SM)

// ---------------- fp16 K-blocked scratch [kt][row][32] (no allocs allowed) ----------------
__device__ __align__(256) __half g_xb[(size_t)BATCH * KD];
__device__ __align__(256) __half g_wb[ND * KD];

// ---------------- helpers ----------------
static __device__ __forceinline__ uint32_t smem_u32(const void* p) {
    uint32_t a;
    asm("{ .reg .u64 t; cvta.to.shared.u64 t, %1; cvt.u32.u64 %0, t; }"
        : "=r"(a) : "l"(p));
    return a;
}

__device__ __forceinline__ void cp16(uint32_t dst, const void* src) {
    asm volatile("cp.async.cg.shared.global [%0], [%1], 16;"
                 :: "r"(dst), "l"(src) : "memory");
}
__device__ __forceinline__ void cp_commit() {
    asm volatile("cp.async.commit_group;" ::: "memory");
}
template <int N>
__device__ __forceinline__ void cp_wait() {
    asm volatile("cp.async.wait_group %0;" :: "n"(N) : "memory");
}

__device__ __forceinline__ void ldsm4(uint32_t& r0, uint32_t& r1, uint32_t& r2,
                                      uint32_t& r3, uint32_t addr) {
    asm volatile("ldmatrix.sync.aligned.m8n8.x4.shared.b16 {%0,%1,%2,%3}, [%4];"
                 : "=r"(r0), "=r"(r1), "=r"(r2), "=r"(r3) : "r"(addr));
}

__device__ __forceinline__ void mma16816(float* d, const uint32_t* a, const uint32_t* b) {
    asm volatile(
        "mma.sync.aligned.m16n8k16.row.col.f32.f16.f16.f32 "
        "{%0,%1,%2,%3}, {%4,%5,%6,%7}, {%8,%9}, {%0,%1,%2,%3};"
        : "+f"(d[0]), "+f"(d[1]), "+f"(d[2]), "+f"(d[3])
        : "r"(a[0]), "r"(a[1]), "r"(a[2]), "r"(a[3]), "r"(b[0]), "r"(b[1]));
}

// ---------------- prepasses: fp32 row-major -> fp16 K-blocked [kt][row][32] ----------------
__global__ void __launch_bounds__(256) cvt_x_kernel(const float* __restrict__ s) {
    size_t idx = (size_t)blockIdx.x * 256 + threadIdx.x;  // one float4 each
    size_t m  = idx >> 7;
    int   c4  = (int)(idx & 127);
    float4 v = reinterpret_cast<const float4*>(s)[idx];
    __half2 h0 = __floats2half2_rn(v.x, v.y);
    __half2 h1 = __floats2half2_rn(v.z, v.w);
    uint2 u;
    u.x = *reinterpret_cast<uint32_t*>(&h0);
    u.y = *reinterpret_cast<uint32_t*>(&h1);
    int kt = c4 >> 3, ci = c4 & 7;
    *reinterpret_cast<uint2*>(g_xb + (size_t)kt * (BATCH * BK) + m * BK + ci * 4) = u;
}

__global__ void __launch_bounds__(256) cvt_w_kernel(const float* __restrict__ s) {
    size_t idx = (size_t)blockIdx.x * 256 + threadIdx.x;
    int n  = (int)(idx >> 7);
    int c4 = (int)(idx & 127);
    float4 v = reinterpret_cast<const float4*>(s)[idx];
    __half2 h0 = __floats2half2_rn(v.x, v.y);
    __half2 h1 = __floats2half2_rn(v.z, v.w);
    uint2 u;
    u.x = *reinterpret_cast<uint32_t*>(&h0);
    u.y = *reinterpret_cast<uint32_t*>(&h1);
    int kt = c4 >> 3, ci = c4 & 7;
    *reinterpret_cast<uint2*>(g_wb + (size_t)kt * (ND * BK) + (size_t)n * BK + ci * 4) = u;
}

// ---------------- GEMM: 128 threads, 3 CTAs/SM, warp tile 64x64 ----------------
// stage tile rows are 64B; 16B chunk c (0..3) of row r at r*64 + ((c ^ ((r>>1)&3))<<4)
__global__ void __launch_bounds__(128, 3)
gemm_f16_kernel(const float* __restrict__ Bv, float* __restrict__ Y) {
    extern __shared__ __align__(1024) char smem[];
    const uint32_t sb = smem_u32(smem);

    const int tid  = threadIdx.x;
    const int wid  = tid >> 5;              // 0..3 -> N offset wid*64
    const int lane = tid & 31;

    const int bm = blockIdx.x >> 1;
    const int bn = blockIdx.x & 1;
    const int row0 = bm * BM;
    const int col0 = bn * BN;

    // staging: A 256 chunks + B 1024 chunks, 128 threads
    const int str = tid >> 2;               // row step base
    const int stc = tid & 3;                // chunk
    auto stageAB = [&](int kt, int slot) {
        const uint32_t base = sb + slot * STAGE;
        const __half* asrc = g_xb + (size_t)kt * (BATCH * BK) + (size_t)row0 * BK;
        const __half* bsrc = g_wb + (size_t)kt * (ND * BK) + (size_t)col0 * BK;
#pragma unroll
        for (int i = 0; i < 2; i++) {        // A: rows str + i*32
            int r = str + i * 32;
            uint32_t dst = base + (uint32_t)(r * 64 + ((stc ^ ((r >> 1) & 3)) << 4));
            cp16(dst, asrc + (size_t)r * BK + stc * 8);
        }
#pragma unroll
        for (int i = 0; i < 8; i++) {        // B: rows str + i*32
            int r = str + i * 32;
            uint32_t dst = base + A_ST + (uint32_t)(r * 64 + ((stc ^ ((r >> 1) & 3)) << 4));
            cp16(dst, bsrc + (size_t)r * BK + stc * 8);
        }
    };

    stageAB(0, 0); cp_commit();
    stageAB(1, 1); cp_commit();

    // fragment addressing
    const int lr  = lane & 15;
    const int lc  = lane >> 4;               // 0/1 -> +16B k-chunk
    const int bsw = (lr >> 1) & 3;           // xor term ((row>>1)&3); tile bases are mult of 16
    uint32_t aRow[4], bRow[8];
#pragma unroll
    for (int mt = 0; mt < 4; mt++)
        aRow[mt] = (uint32_t)((mt * 16 + lr) * 64);
#pragma unroll
    for (int np = 0; np < 4; np++)
        bRow[np] = (uint32_t)((wid * 64 + np * 16 + lr) * 64) + A_ST;

    float acc[4][8][4];
#pragma unroll
    for (int i = 0; i < 4; i++)
#pragma unroll
        for (int j = 0; j < 8; j++)
#pragma unroll
            for (int e = 0; e < 4; e++) acc[i][j][e] = 0.0f;

    for (int kt = 0; kt < NKITER; kt++) {
        cp_wait<1>();
        __syncthreads();
        if (kt + 2 < NKITER) stageAB(kt + 2, (kt + 2) % STAGES);
        cp_commit();

        const uint32_t base = sb + (kt % STAGES) * STAGE;
#pragma unroll
        for (int ks = 0; ks < 2; ks++) {
            const uint32_t koff = (uint32_t)(((ks * 2 + lc) ^ bsw) << 4);
            uint32_t af[4][4];
#pragma unroll
            for (int mt = 0; mt < 4; mt++)
                ldsm4(af[mt][0], af[mt][1], af[mt][2], af[mt][3],
                      base + aRow[mt] + koff);
            // B loaded one ldsm4 at a time to bound register liveness
#pragma unroll
            for (int np = 0; np < 4; np++) {
                uint32_t bf[4];
                ldsm4(bf[0], bf[1], bf[2], bf[3], base + bRow[np] + koff);
#pragma unroll
                for (int j = 0; j < 2; j++) {
                    uint32_t bb[2] = { bf[j], bf[j + 2] };
#pragma unroll
                    for (int mt = 0; mt < 4; mt++)
                        mma16816(acc[mt][np * 2 + j], af[mt], bb);
                }
            }
        }
    }

    // epilogue: bias + fp32 store (warp covers 64 rows x 64 cols)
    const int ccol = col0 + wid * 64;
#pragma unroll
    for (int nt = 0; nt < 8; nt++) {
        const int c = ccol + nt * 8 + (lane & 3) * 2;
        const float2 bv = *reinterpret_cast<const float2*>(Bv + c);
#pragma unroll
        for (int mt = 0; mt < 4; mt++) {
            const int r = row0 + mt * 16 + (lane >> 2);
            float2 v0, v1;
            v0.x = acc[mt][nt][0] + bv.x;
            v0.y = acc[mt][nt][1] + bv.y;
            v1.x = acc[mt][nt][2] + bv.x;
            v1.y = acc[mt][nt][3] + bv.y;
            *reinterpret_cast<float2*>(Y + (size_t)r * ND + c) = v0;
            *reinterpret_cast<float2*>(Y + (size_t)(r + 8) * ND + c) = v1;
        }
    }
}

extern "C" void kernel_launch(void* const* d_in, const int* in_sizes, int n_in,
                              void* d_out, int out_size) {
    const float* x = nullptr;
    const float* w = nullptr;
    const float* b = nullptr;
    for (int i = 0; i < n_in; i++) {
        if (in_sizes[i] == BATCH * KD)   x = (const float*)d_in[i];
        else if (in_sizes[i] == ND * KD) w = (const float*)d_in[i];
        else if (in_sizes[i] == ND)      b = (const float*)d_in[i];
    }
    float* out = (float*)d_out;

    cvt_x_kernel<<<(BATCH * KD / 4) / 256, 256>>>(x);   // ~31 us, near HBM floor
    cvt_w_kernel<<<(ND * KD / 4) / 256, 256>>>(w);      // ~1 us

    cudaFuncSetAttribute(gemm_f16_kernel,
                         cudaFuncAttributeMaxDynamicSharedMemorySize, SMEM_TOTAL);
    gemm_f16_kernel<<<(BATCH / BM) * (ND / BN), 128, SMEM_TOTAL>>>(b, out);
}